// round 9
// baseline (speedup 1.0000x reference)
#include <cuda_runtime.h>
#include <math.h>

#define NB 2048
#define FULLMASK 0xffffffffu

// ------------- scratch -------------
__device__ float g_crops[NB*48*48*3];
__device__ float g_bb[NB*4];
__device__ float g_p1[NB*23*23*32];
__device__ float g_p2[NB*10*10*64];
__device__ float g_h4[NB*1152];
__device__ float g_h5[NB*256];
__device__ float4 g_outbox[NB];
__device__ float  g_key[NB];
__device__ int    g_order[NB];
__device__ float  g_sortkey[NB];
__device__ float4 g_sortedbox[NB];
__device__ unsigned g_mask[NB*64];
__device__ unsigned g_keep[64];

__device__ __forceinline__ void fma4(float4& v, float s, const float4 wv) {
    v.x = fmaf(s, wv.x, v.x); v.y = fmaf(s, wv.y, v.y);
    v.z = fmaf(s, wv.z, v.z); v.w = fmaf(s, wv.w, v.w);
}
__device__ __forceinline__ void prelu4(float4& v, const float4 al) {
    v.x = v.x >= 0.f ? v.x : al.x * v.x; v.y = v.y >= 0.f ? v.y : al.y * v.y;
    v.z = v.z >= 0.f ? v.z : al.z * v.z; v.w = v.w >= 0.f ? v.w : al.w * v.w;
}
__device__ __forceinline__ void max4(float4& m, const float4 v) {
    m.x = fmaxf(m.x, v.x); m.y = fmaxf(m.y, v.y);
    m.z = fmaxf(m.z, v.z); m.w = fmaxf(m.w, v.w);
}

// ------------- K1: crop + normalize -------------
__global__ void k_crop(const float* __restrict__ bboxes, const float* __restrict__ image) {
    int n = blockIdx.x, tid = threadIdx.x;
    __shared__ int sxs[48], sys[48];
    __shared__ float sbb[4];
    if (tid < 4) {
        float v = bboxes[n*4 + tid];
        v = (tid < 2) ? fmaxf(v, 0.f) : fminf(v, 1024.f);
        sbb[tid] = v; g_bb[n*4 + tid] = v;
    }
    __syncthreads();
    if (tid < 48) {
        int ix1 = (int)sbb[0], iy1 = (int)sbb[1], ix2 = (int)sbb[2], iy2 = (int)sbb[3];
        int cw = max(ix2 - ix1, 1), ch = max(iy2 - iy1, 1);
        sxs[tid] = ix1 + (tid * cw) / 48;
        sys[tid] = iy1 + (tid * ch) / 48;
    }
    __syncthreads();
    for (int p = tid; p < 48*48; p += blockDim.x) {
        int i = p / 48, j = p - i*48;
        const float* src = image + (sys[i]*1024 + sxs[j])*3;
        float* dst = g_crops + (size_t)((n*48 + i)*48 + j)*3;
        dst[0] = (src[0] - 127.5f) * 0.0078125f;
        dst[1] = (src[1] - 127.5f) * 0.0078125f;
        dst[2] = (src[2] - 127.5f) * 0.0078125f;
    }
}

// ------------- K2: conv1(3x3,3->32)+prelu -> smem, then pool(3,2,p1) -> 23x23x32
// 2 passes x 16 oc; per thread: 2 oc4 accumulators.
__global__ void __launch_bounds__(512, 1)
k_c1p1(const float* __restrict__ w1, const float* __restrict__ b1,
       const float* __restrict__ a1) {
    extern __shared__ float dsm[];
    float* sc = dsm;                         // 6912
    float4* sw = (float4*)(dsm + 6912);      // 216 f4
    float4* sb4 = sw + 216;                  // 8
    float4* sa4 = sb4 + 8;                   // 8
    float4* cbuf = sa4 + 8;                  // 46*46*4 = 8464 f4
    int n = blockIdx.x, tid = threadIdx.x;
    const float4* src = (const float4*)(g_crops + (size_t)n*6912);
    for (int i = tid; i < 1728; i += 512) ((float4*)sc)[i] = src[i];
    for (int i = tid; i < 216; i += 512) sw[i] = ((const float4*)w1)[i];
    if (tid < 8) { sb4[tid] = ((const float4*)b1)[tid]; sa4[tid] = ((const float4*)a1)[tid]; }
    __syncthreads();
    #pragma unroll
    for (int pass = 0; pass < 2; pass++) {
        int ocb = pass * 4;
        for (int it = tid; it < 46*46*2; it += 512) {
            int pr = it & 1, pos = it >> 1, r = pos / 46, c = pos - r*46;
            int o0 = ocb + 2*pr;
            float4 v0 = sb4[o0], v1 = sb4[o0+1];
            #pragma unroll
            for (int ky = 0; ky < 3; ky++)
            #pragma unroll
            for (int kx = 0; kx < 3; kx++) {
                const float* ip = sc + ((r+ky)*48 + (c+kx))*3;
                int wi = ((ky*3 + kx)*3)*8 + o0;
                fma4(v0, ip[0], sw[wi]);      fma4(v1, ip[0], sw[wi+1]);
                fma4(v0, ip[1], sw[wi+8]);    fma4(v1, ip[1], sw[wi+9]);
                fma4(v0, ip[2], sw[wi+16]);   fma4(v1, ip[2], sw[wi+17]);
            }
            prelu4(v0, sa4[o0]); prelu4(v1, sa4[o0+1]);
            cbuf[pos*4 + 2*pr] = v0;
            cbuf[pos*4 + 2*pr + 1] = v1;
        }
        __syncthreads();
        for (int it = tid; it < 23*23*4; it += 512) {
            int oc4 = it & 3, p = it >> 2, i = p % 23, j = p / 23;
            float4 m = make_float4(-3.4e38f, -3.4e38f, -3.4e38f, -3.4e38f);
            #pragma unroll
            for (int dr = -1; dr < 2; dr++) {
                int r = 2*j + dr; if (r < 0 || r > 45) continue;
                #pragma unroll
                for (int dc = -1; dc < 2; dc++) {
                    int c = 2*i + dc; if (c < 0 || c > 45) continue;
                    max4(m, cbuf[(r*46 + c)*4 + oc4]);
                }
            }
            ((float4*)(g_p1 + (size_t)n*16928))[(j*23 + i)*8 + ocb + oc4] = m;
        }
        __syncthreads();
    }
}

// ------------- K3: conv2(3x3,32->64)+prelu -> smem, then pool(3,2,p0) -> 10x10x64
// Input rows padded 32->36 floats (bank-conflict-free float4 ic loads); 2x oc4 tiling.
__global__ void __launch_bounds__(512, 1)
k_c2p2(const float* __restrict__ w2, const float* __restrict__ b2,
       const float* __restrict__ a2) {
    extern __shared__ float dsm[];
    float* sp1 = dsm;                       // 529*36 = 19044 floats (padded)
    float4* sw2 = (float4*)(dsm + 19044);   // 4608 f4
    float4* sb = sw2 + 4608;                // 16
    float4* sa = sb + 16;                   // 16
    float4* cbuf = sa + 16;                 // 21*21*8 = 3528 f4
    int n = blockIdx.x, tid = threadIdx.x;
    const float4* src = (const float4*)(g_p1 + (size_t)n*16928);
    for (int i = tid; i < 529*8; i += 512) {
        int pos = i >> 3, sub = i & 7;
        ((float4*)sp1)[pos*9 + sub] = src[i];
    }
    for (int i = tid; i < 4608; i += 512) sw2[i] = ((const float4*)w2)[i];
    if (tid < 16) { sb[tid] = ((const float4*)b2)[tid]; sa[tid] = ((const float4*)a2)[tid]; }
    __syncthreads();
    #pragma unroll
    for (int pass = 0; pass < 2; pass++) {
        int ocb = pass * 8;
        for (int it = tid; it < 21*21*4; it += 512) {
            int pr = it & 3, pos = it >> 2, r = pos / 21, c = pos - r*21;
            int o0 = ocb + 2*pr;
            float4 v0 = sb[o0], v1 = sb[o0+1];
            #pragma unroll
            for (int ky = 0; ky < 3; ky++)
            #pragma unroll
            for (int kx = 0; kx < 3; kx++) {
                const float4* ip4 = (const float4*)(sp1 + ((r+ky)*23 + (c+kx))*36);
                const float4* wp = sw2 + ((ky*3 + kx)*32)*16 + o0;
                #pragma unroll
                for (int ic4 = 0; ic4 < 8; ic4++) {
                    float4 iv = ip4[ic4];
                    const float4* w4 = wp + ic4*64;
                    fma4(v0, iv.x, w4[0]);  fma4(v1, iv.x, w4[1]);
                    fma4(v0, iv.y, w4[16]); fma4(v1, iv.y, w4[17]);
                    fma4(v0, iv.z, w4[32]); fma4(v1, iv.z, w4[33]);
                    fma4(v0, iv.w, w4[48]); fma4(v1, iv.w, w4[49]);
                }
            }
            prelu4(v0, sa[o0]); prelu4(v1, sa[o0+1]);
            cbuf[pos*8 + 2*pr] = v0;
            cbuf[pos*8 + 2*pr + 1] = v1;
        }
        __syncthreads();
        for (int it = tid; it < 10*10*8; it += 512) {
            int oc4 = it & 7, p = it >> 3, i = p % 10, j = p / 10;
            float4 m = cbuf[((2*j)*21 + 2*i)*8 + oc4];
            #pragma unroll
            for (int dr = 0; dr < 3; dr++)
            #pragma unroll
            for (int dc = 0; dc < 3; dc++) {
                if (dr == 0 && dc == 0) continue;
                max4(m, cbuf[((2*j+dr)*21 + 2*i+dc)*8 + oc4]);
            }
            ((float4*)(g_p2 + (size_t)n*6400))[(j*10 + i)*16 + ocb + oc4] = m;
        }
        __syncthreads();
    }
}

// ------------- K4: conv3+prelu+pool(2,2) + conv4+prelu + NCHW flatten
// Input rows padded 64->68 floats; conv3 with 2x oc4 tiling, float4 ic loads.
__global__ void __launch_bounds__(512, 1)
k_c3c4(const float* __restrict__ w3, const float* __restrict__ b3,
       const float* __restrict__ a3, const float* __restrict__ w4,
       const float* __restrict__ b4, const float* __restrict__ a4) {
    extern __shared__ float dsm[];
    float* sp2 = dsm;                       // 100*68 = 6800 floats (padded)
    float4* sw3 = (float4*)(dsm + 6800);    // 9216 f4
    float* c3b = (float*)(sw3 + 9216);      // 4096
    float* p3  = c3b + 4096;                // 1024
    int n = blockIdx.x, tid = threadIdx.x;
    const float4* src = (const float4*)(g_p2 + (size_t)n*6400);
    for (int i = tid; i < 100*16; i += 512) {
        int pos = i >> 4, sub = i & 15;
        ((float4*)sp2)[pos*17 + sub] = src[i];
    }
    for (int i = tid; i < 9216; i += 512) sw3[i] = ((const float4*)w3)[i];
    __syncthreads();
    // conv3: 8x8 pos x 16 oc4 ; each thread: 1 pos x 2 oc4
    for (int it = tid; it < 8*8*8; it += 512) {
        int pr = it & 7, pos = it >> 3, x = pos % 8, y = pos / 8;
        int o0 = 2*pr;
        float4 v0 = ((const float4*)b3)[o0], v1 = ((const float4*)b3)[o0+1];
        #pragma unroll
        for (int ky = 0; ky < 3; ky++)
        #pragma unroll
        for (int kx = 0; kx < 3; kx++) {
            const float4* ip4 = (const float4*)(sp2 + ((y+ky)*10 + x+kx)*68);
            const float4* wp = sw3 + ((ky*3 + kx)*64)*16 + o0;
            #pragma unroll 4
            for (int ic4 = 0; ic4 < 16; ic4++) {
                float4 iv = ip4[ic4];
                const float4* w4 = wp + ic4*64;
                fma4(v0, iv.x, w4[0]);  fma4(v1, iv.x, w4[1]);
                fma4(v0, iv.y, w4[16]); fma4(v1, iv.y, w4[17]);
                fma4(v0, iv.z, w4[32]); fma4(v1, iv.z, w4[33]);
                fma4(v0, iv.w, w4[48]); fma4(v1, iv.w, w4[49]);
            }
        }
        prelu4(v0, ((const float4*)a3)[o0]); prelu4(v1, ((const float4*)a3)[o0+1]);
        ((float4*)c3b)[(y*8 + x)*16 + o0] = v0;
        ((float4*)c3b)[(y*8 + x)*16 + o0 + 1] = v1;
    }
    __syncthreads();
    // pool 2x2 -> 4x4x64
    for (int it = tid; it < 4*4*16; it += 512) {
        int oc4 = it & 15, p = it >> 4, x = p % 4, y = p / 4;
        const float4* c4 = (const float4*)c3b;
        float4 m = c4[(2*y*8 + 2*x)*16 + oc4];
        max4(m, c4[(2*y*8 + 2*x+1)*16 + oc4]);
        max4(m, c4[((2*y+1)*8 + 2*x)*16 + oc4]);
        max4(m, c4[((2*y+1)*8 + 2*x+1)*16 + oc4]);
        ((float4*)p3)[(y*4 + x)*16 + oc4] = m;
    }
    __syncthreads();
    // conv4 2x2,64->128 -> 3x3x128, flatten NCHW (c*9 + y*3 + x)
    for (int it = tid; it < 3*3*32; it += 512) {
        int oc4 = it & 31, p = it >> 5, x = p % 3, y = p / 3;
        float4 v = __ldg((const float4*)b4 + oc4);
        #pragma unroll
        for (int ky = 0; ky < 2; ky++)
        #pragma unroll
        for (int kx = 0; kx < 2; kx++) {
            const float* ip = p3 + ((y+ky)*4 + x+kx)*64;
            const float4* wp = (const float4*)w4 + ((ky*2 + kx)*64)*32 + oc4;
            #pragma unroll 8
            for (int ic = 0; ic < 64; ic++)
                fma4(v, ip[ic], __ldg(wp + ic*32));
        }
        float4 al = __ldg((const float4*)a4 + oc4);
        prelu4(v, al);
        float* hb = g_h4 + (size_t)n*1152;
        int c = oc4*4;
        hb[(c+0)*9 + y*3 + x] = v.x;
        hb[(c+1)*9 + y*3 + x] = v.y;
        hb[(c+2)*9 + y*3 + x] = v.z;
        hb[(c+3)*9 + y*3 + x] = v.w;
    }
}

// ------------- K5: fc5 (1152->256) + prelu, 8 boxes/block -------------
__global__ void k_fc5(const float* __restrict__ w, const float* __restrict__ b,
                      const float* __restrict__ a) {
    __shared__ float sa_[8*1152];
    int b0 = blockIdx.x * 8, tid = threadIdx.x;
    const float4* src = (const float4*)(g_h4 + (size_t)b0*1152);
    for (int i = tid; i < 2304; i += 256) ((float4*)sa_)[i] = src[i];
    __syncthreads();
    int o = tid;
    float bias = __ldg(b + o);
    float acc[8];
    #pragma unroll
    for (int q = 0; q < 8; q++) acc[q] = bias;
    const float4* wr = (const float4*)(w + (size_t)o*1152);
    for (int k4 = 0; k4 < 288; k4++) {
        float4 wv = __ldg(wr + k4);
        #pragma unroll
        for (int q = 0; q < 8; q++) {
            float4 av = ((const float4*)(sa_ + q*1152))[k4];
            acc[q] = fmaf(wv.x, av.x, acc[q]);
            acc[q] = fmaf(wv.y, av.y, acc[q]);
            acc[q] = fmaf(wv.z, av.z, acc[q]);
            acc[q] = fmaf(wv.w, av.w, acc[q]);
        }
    }
    float al = __ldg(a + o);
    #pragma unroll
    for (int q = 0; q < 8; q++) {
        float v = acc[q];
        g_h5[(size_t)(b0 + q)*256 + o] = v >= 0.f ? v : al * v;
    }
}

// ------------- K6: heads -------------
__global__ void k_heads(const float* __restrict__ wa, const float* __restrict__ ba,
                        const float* __restrict__ wb, const float* __restrict__ bbv) {
    int n = blockIdx.x * 8 + (threadIdx.x >> 5);
    int lane = threadIdx.x & 31;
    float h[8];
    #pragma unroll
    for (int u = 0; u < 8; u++) h[u] = g_h5[(size_t)n*256 + lane + u*32];
    float dots[6];
    #pragma unroll
    for (int d = 0; d < 6; d++) {
        const float* wr = (d < 2) ? (wa + d*256) : (wb + (d-2)*256);
        float p = 0.f;
        #pragma unroll
        for (int u = 0; u < 8; u++) p = fmaf(h[u], __ldg(wr + lane + u*32), p);
        #pragma unroll
        for (int off = 16; off; off >>= 1) p += __shfl_xor_sync(FULLMASK, p, off);
        dots[d] = p;
    }
    if (lane == 0) {
        float z0 = dots[0] + __ldg(ba+0), z1 = dots[1] + __ldg(ba+1);
        float m = fmaxf(z0, z1);
        float e0 = expf(z0 - m), e1 = expf(z1 - m);
        float score = e1 / (e0 + e1);
        float r0 = dots[2] + __ldg(bbv+0), r1 = dots[3] + __ldg(bbv+1);
        float r2 = dots[4] + __ldg(bbv+2), r3 = dots[5] + __ldg(bbv+3);
        float x1 = g_bb[n*4+0], y1 = g_bb[n*4+1], x2 = g_bb[n*4+2], y2 = g_bb[n*4+3];
        float w = x2 - x1, hh = y2 - y1;
        g_outbox[n] = make_float4(fmaf(r0,w,x1), fmaf(r1,hh,y1), fmaf(r2,w,x2), fmaf(r3,hh,y2));
        g_key[n] = (score >= 0.5f) ? score : -INFINITY;
    }
}

// ------------- K7: bitonic sort by (key desc, idx asc) -------------
__device__ __forceinline__ bool s_before(float ka, int ia, float kb, int ib) {
    return (ka > kb) || (ka == kb && ia < ib);
}
__global__ void k_sort() {
    __shared__ float sk[NB];
    __shared__ int si[NB];
    int tid = threadIdx.x;
    for (int i = tid; i < NB; i += 1024) { sk[i] = g_key[i]; si[i] = i; }
    for (int k = 2; k <= NB; k <<= 1)
        for (int j = k >> 1; j > 0; j >>= 1) {
            __syncthreads();
            for (int i = tid; i < NB; i += 1024) {
                int l = i ^ j;
                if (l > i) {
                    bool asc = ((i & k) == 0);
                    bool ib = s_before(sk[i], si[i], sk[l], si[l]);
                    if (ib != asc) {
                        float tk = sk[i]; sk[i] = sk[l]; sk[l] = tk;
                        int ti = si[i]; si[i] = si[l]; si[l] = ti;
                    }
                }
            }
        }
    __syncthreads();
    for (int r = tid; r < NB; r += 1024) {
        g_sortkey[r] = sk[r];
        g_order[r] = si[r];
        g_sortedbox[r] = g_outbox[si[r]];
    }
}

// ------------- K8: IoU suppression mask -------------
__global__ void k_mask() {
    int t = blockIdx.x * 256 + threadIdx.x;
    int i = t >> 6, wj = t & 63;
    float4 bi = g_sortedbox[i];
    float ai = (bi.z - bi.x) * (bi.w - bi.y);
    unsigned bits = 0;
    for (int u = 0; u < 32; u++) {
        int j = wj*32 + u;
        if (j > i) {
            float4 bj = g_sortedbox[j];
            float aj = (bj.z - bj.x) * (bj.w - bj.y);
            float xx1 = fmaxf(bi.x, bj.x), yy1 = fmaxf(bi.y, bj.y);
            float xx2 = fminf(bi.z, bj.z), yy2 = fminf(bi.w, bj.w);
            float inter = fmaxf(xx2 - xx1, 0.f) * fmaxf(yy2 - yy1, 0.f);
            float iou = inter / (ai + aj - inter + 1e-12f);
            if (iou > 0.5f) bits |= (1u << u);
        }
    }
    g_mask[i*64 + wj] = bits;
}

// ------------- K9: serial greedy scan (single warp) -------------
__global__ void k_scan() {
    int lane = threadIdx.x;
    unsigned r0 = 0, r1 = 0, k0 = 0, k1 = 0;
    for (int i = 0; i < NB; i++) {
        int wi = i >> 5;
        unsigned cur = (wi >= 32) ? r1 : r0;
        unsigned word = __shfl_sync(FULLMASK, cur, wi & 31);
        bool removed = (word >> (i & 31)) & 1u;
        bool valid = g_sortkey[i] >= 0.5f;
        bool kept = valid && !removed;
        if (kept) {
            r0 |= g_mask[i*64 + lane];
            r1 |= g_mask[i*64 + 32 + lane];
            if (lane == (wi & 31)) {
                if (wi >= 32) k1 |= (1u << (i & 31)); else k0 |= (1u << (i & 31));
            }
        }
    }
    g_keep[lane] = k0;
    g_keep[32 + lane] = k1;
}

// ------------- K10: scatter output -------------
__global__ void k_out(float4* __restrict__ out) {
    int r = blockIdx.x * 256 + threadIdx.x;
    int orig = g_order[r];
    bool kept = (g_keep[r >> 5] >> (r & 31)) & 1u;
    float4 b = g_sortedbox[r];
    out[orig] = kept ? b : make_float4(0.f, 0.f, 0.f, 0.f);
}

extern "C" void kernel_launch(void* const* d_in, const int* in_sizes, int n_in,
                              void* d_out, int out_size) {
    const float* bboxes  = (const float*)d_in[0];
    const float* image   = (const float*)d_in[1];
    const float* c1w = (const float*)d_in[2];  const float* c1b = (const float*)d_in[3];
    const float* p1  = (const float*)d_in[4];
    const float* c2w = (const float*)d_in[5];  const float* c2b = (const float*)d_in[6];
    const float* p2  = (const float*)d_in[7];
    const float* c3w = (const float*)d_in[8];  const float* c3b = (const float*)d_in[9];
    const float* p3  = (const float*)d_in[10];
    const float* c4w = (const float*)d_in[11]; const float* c4b = (const float*)d_in[12];
    const float* p4  = (const float*)d_in[13];
    const float* f5w = (const float*)d_in[14]; const float* f5b = (const float*)d_in[15];
    const float* p5  = (const float*)d_in[16];
    const float* f6aw = (const float*)d_in[17]; const float* f6ab = (const float*)d_in[18];
    const float* f6bw = (const float*)d_in[19]; const float* f6bb = (const float*)d_in[20];

    int smem1 = (6912 + 216*4 + 8*4 + 8*4 + 8464*4) * 4;     // 166784
    int smem2 = (19044 + (4608 + 32 + 3528) * 4) * 4;        // 206864
    int smem3 = (6800 + 9216*4 + 4096 + 1024) * 4;           // 195136
    cudaFuncSetAttribute(k_c1p1, cudaFuncAttributeMaxDynamicSharedMemorySize, smem1);
    cudaFuncSetAttribute(k_c2p2, cudaFuncAttributeMaxDynamicSharedMemorySize, smem2);
    cudaFuncSetAttribute(k_c3c4, cudaFuncAttributeMaxDynamicSharedMemorySize, smem3);

    k_crop<<<NB, 256>>>(bboxes, image);
    k_c1p1<<<NB, 512, smem1>>>(c1w, c1b, p1);
    k_c2p2<<<NB, 512, smem2>>>(c2w, c2b, p2);
    k_c3c4<<<NB, 512, smem3>>>(c3w, c3b, p3, c4w, c4b, p4);
    k_fc5<<<NB/8, 256>>>(f5w, f5b, p5);
    k_heads<<<NB/8, 256>>>(f6aw, f6ab, f6bw, f6bb);
    k_sort<<<1, 1024>>>();
    k_mask<<<NB*64/256, 256>>>();
    k_scan<<<1, 32>>>();
    k_out<<<NB/256, 256>>>((float4*)d_out);
}

// round 11
// speedup vs baseline: 3.5284x; 3.5284x over previous
#include <cuda_runtime.h>
#include <math.h>

#define NB 2048
#define FULLMASK 0xffffffffu

// ------------- scratch -------------
__device__ float g_crops[NB*48*48*3];
__device__ float g_bb[NB*4];
__device__ float g_p1[NB*23*23*32];
__device__ float g_p2[NB*10*10*64];
__device__ float g_h4[NB*1152];
__device__ float g_h5[NB*256];
__device__ float4 g_outbox[NB];
__device__ float  g_key[NB];
__device__ int    g_order[NB];
__device__ float  g_sortkey[NB];
__device__ float4 g_sortedbox[NB];
__device__ unsigned g_mask[NB*64];
__device__ unsigned g_keep[64];

__device__ __forceinline__ void fma4(float4& v, float s, const float4 wv) {
    v.x = fmaf(s, wv.x, v.x); v.y = fmaf(s, wv.y, v.y);
    v.z = fmaf(s, wv.z, v.z); v.w = fmaf(s, wv.w, v.w);
}
__device__ __forceinline__ void prelu4(float4& v, const float4 al) {
    v.x = v.x >= 0.f ? v.x : al.x * v.x; v.y = v.y >= 0.f ? v.y : al.y * v.y;
    v.z = v.z >= 0.f ? v.z : al.z * v.z; v.w = v.w >= 0.f ? v.w : al.w * v.w;
}
__device__ __forceinline__ void max4(float4& m, const float4 v) {
    m.x = fmaxf(m.x, v.x); m.y = fmaxf(m.y, v.y);
    m.z = fmaxf(m.z, v.z); m.w = fmaxf(m.w, v.w);
}

// ------------- K1: crop + normalize -------------
__global__ void k_crop(const float* __restrict__ bboxes, const float* __restrict__ image) {
    int n = blockIdx.x, tid = threadIdx.x;
    __shared__ int sxs[48], sys[48];
    __shared__ float sbb[4];
    if (tid < 4) {
        float v = bboxes[n*4 + tid];
        v = (tid < 2) ? fmaxf(v, 0.f) : fminf(v, 1024.f);
        sbb[tid] = v; g_bb[n*4 + tid] = v;
    }
    __syncthreads();
    if (tid < 48) {
        int ix1 = (int)sbb[0], iy1 = (int)sbb[1], ix2 = (int)sbb[2], iy2 = (int)sbb[3];
        int cw = max(ix2 - ix1, 1), ch = max(iy2 - iy1, 1);
        sxs[tid] = ix1 + (tid * cw) / 48;
        sys[tid] = iy1 + (tid * ch) / 48;
    }
    __syncthreads();
    for (int p = tid; p < 48*48; p += blockDim.x) {
        int i = p / 48, j = p - i*48;
        const float* src = image + (sys[i]*1024 + sxs[j])*3;
        float* dst = g_crops + (size_t)((n*48 + i)*48 + j)*3;
        dst[0] = (src[0] - 127.5f) * 0.0078125f;
        dst[1] = (src[1] - 127.5f) * 0.0078125f;
        dst[2] = (src[2] - 127.5f) * 0.0078125f;
    }
}

// ------------- K2: conv1(3x3,3->32)+prelu -> smem, then pool(3,2,p1) -> 23x23x32
// (exactly the R8 version — known good)
__global__ void __launch_bounds__(512, 1)
k_c1p1(const float* __restrict__ w1, const float* __restrict__ b1,
       const float* __restrict__ a1) {
    extern __shared__ float dsm[];
    float* sc = dsm;                         // 6912
    float4* sw = (float4*)(dsm + 6912);      // 216 f4
    float4* sb4 = sw + 216;                  // 8
    float4* sa4 = sb4 + 8;                   // 8
    float4* cbuf = sa4 + 8;                  // 46*46*4 = 8464 f4
    int n = blockIdx.x, tid = threadIdx.x;
    const float4* src = (const float4*)(g_crops + (size_t)n*6912);
    for (int i = tid; i < 1728; i += 512) ((float4*)sc)[i] = src[i];
    for (int i = tid; i < 216; i += 512) sw[i] = ((const float4*)w1)[i];
    if (tid < 8) { sb4[tid] = ((const float4*)b1)[tid]; sa4[tid] = ((const float4*)a1)[tid]; }
    __syncthreads();
    #pragma unroll
    for (int pass = 0; pass < 2; pass++) {
        int ocb = pass * 4;
        for (int it = tid; it < 46*46*4; it += 512) {
            int oc4 = it & 3, pos = it >> 2, r = pos / 46, c = pos - r*46;
            float4 v = sb4[ocb + oc4];
            #pragma unroll
            for (int ky = 0; ky < 3; ky++)
            #pragma unroll
            for (int kx = 0; kx < 3; kx++) {
                const float* ip = sc + ((r+ky)*48 + (c+kx))*3;
                int wi = ((ky*3 + kx)*3)*8 + ocb + oc4;
                fma4(v, ip[0], sw[wi]);
                fma4(v, ip[1], sw[wi + 8]);
                fma4(v, ip[2], sw[wi + 16]);
            }
            prelu4(v, sa4[ocb + oc4]);
            cbuf[pos*4 + oc4] = v;
        }
        __syncthreads();
        for (int it = tid; it < 23*23*4; it += 512) {
            int oc4 = it & 3, p = it >> 2, i = p % 23, j = p / 23;
            float4 m = make_float4(-3.4e38f, -3.4e38f, -3.4e38f, -3.4e38f);
            #pragma unroll
            for (int dr = -1; dr < 2; dr++) {
                int r = 2*j + dr; if (r < 0 || r > 45) continue;
                #pragma unroll
                for (int dc = -1; dc < 2; dc++) {
                    int c = 2*i + dc; if (c < 0 || c > 45) continue;
                    max4(m, cbuf[(r*46 + c)*4 + oc4]);
                }
            }
            ((float4*)(g_p1 + (size_t)n*16928))[(j*23 + i)*8 + ocb + oc4] = m;
        }
        __syncthreads();
    }
}

// ------------- K3: conv2(3x3,32->64)+prelu -> smem, then pool(3,2,p0) -> 10x10x64
// Warp-per-oc4-pair, lane-per-4-positions. Weights broadcast; inputs float4 @144B stride.
__global__ void __launch_bounds__(512, 1)
k_c2p2(const float* __restrict__ w2, const float* __restrict__ b2,
       const float* __restrict__ a2) {
    extern __shared__ float dsm[];
    float* sp1 = dsm;                       // 529*36 = 19044 floats (padded rows)
    float4* sw2 = (float4*)(dsm + 19044);   // 4608 f4
    float4* sb = sw2 + 4608;                // 16
    float4* sa = sb + 16;                   // 16
    float4* cbuf = sa + 16;                 // 441*9 = 3969 f4 (padded)
    int n = blockIdx.x, tid = threadIdx.x;
    const float4* src = (const float4*)(g_p1 + (size_t)n*16928);
    for (int i = tid; i < 529*8; i += 512) {
        int pos = i >> 3, sub = i & 7;
        ((float4*)sp1)[pos*9 + sub] = src[i];
    }
    for (int i = tid; i < 4608; i += 512) sw2[i] = ((const float4*)w2)[i];
    if (tid < 16) { sb[tid] = ((const float4*)b2)[tid]; sa[tid] = ((const float4*)a2)[tid]; }
    __syncthreads();
    int w = tid >> 5, lane = tid & 31;
    int chunk = w >> 2;              // 0..3 : positions [chunk*128, chunk*128+128)
    int ocp = w & 3;                 // oc4 pair index
    // lane position bases (clamped; clamped lanes skip the store)
    int posr[4], ib[4];
    #pragma unroll
    for (int t = 0; t < 4; t++) {
        int pos = chunk*128 + lane + 32*t;
        posr[t] = pos;
        int pc = pos > 440 ? 440 : pos;
        int r = pc / 21, c = pc - r*21;
        ib[t] = (r*23 + c)*36;
    }
    #pragma unroll
    for (int pass = 0; pass < 2; pass++) {
        int oc4a = pass*8 + 2*ocp;
        float4 a0[4], a1[4];
        float4 bias0 = sb[oc4a], bias1 = sb[oc4a+1];
        #pragma unroll
        for (int t = 0; t < 4; t++) { a0[t] = bias0; a1[t] = bias1; }
        #pragma unroll
        for (int ky = 0; ky < 3; ky++)
        #pragma unroll
        for (int kx = 0; kx < 3; kx++) {
            int koff = (ky*23 + kx)*36;
            const float4* wp = sw2 + ((ky*3 + kx)*32)*16 + oc4a;
            #pragma unroll
            for (int ic4 = 0; ic4 < 8; ic4++) {
                const float4* w4 = wp + ic4*64;
                float4 wa0 = w4[0],  wb0 = w4[1];
                float4 wa1 = w4[16], wb1 = w4[17];
                float4 wa2 = w4[32], wb2 = w4[33];
                float4 wa3 = w4[48], wb3 = w4[49];
                #pragma unroll
                for (int t = 0; t < 4; t++) {
                    float4 iv = *(const float4*)(sp1 + ib[t] + koff + ic4*4);
                    fma4(a0[t], iv.x, wa0); fma4(a1[t], iv.x, wb0);
                    fma4(a0[t], iv.y, wa1); fma4(a1[t], iv.y, wb1);
                    fma4(a0[t], iv.z, wa2); fma4(a1[t], iv.z, wb2);
                    fma4(a0[t], iv.w, wa3); fma4(a1[t], iv.w, wb3);
                }
            }
        }
        float4 al0 = sa[oc4a], al1 = sa[oc4a+1];
        #pragma unroll
        for (int t = 0; t < 4; t++) {
            if (posr[t] < 441) {
                float4 v0 = a0[t]; prelu4(v0, al0);
                float4 v1 = a1[t]; prelu4(v1, al1);
                cbuf[posr[t]*9 + 2*ocp]     = v0;
                cbuf[posr[t]*9 + 2*ocp + 1] = v1;
            }
        }
        __syncthreads();
        // pool(3,2,pad=0) -> 10x10, this pass's 8 oc4
        for (int it = tid; it < 10*10*8; it += 512) {
            int oc4l = it & 7, p = it >> 3, i = p % 10, j = p / 10;
            float4 m = cbuf[((2*j)*21 + 2*i)*9 + oc4l];
            #pragma unroll
            for (int dr = 0; dr < 3; dr++)
            #pragma unroll
            for (int dc = 0; dc < 3; dc++) {
                if (dr == 0 && dc == 0) continue;
                max4(m, cbuf[((2*j+dr)*21 + 2*i+dc)*9 + oc4l]);
            }
            ((float4*)(g_p2 + (size_t)n*6400))[(j*10 + i)*16 + pass*8 + oc4l] = m;
        }
        __syncthreads();
    }
}

// ------------- K4: conv3(warp-per-oc4-pair)+prelu+pool(2,2) + conv4+prelu + NCHW flatten
__global__ void __launch_bounds__(512, 1)
k_c3c4(const float* __restrict__ w3, const float* __restrict__ b3,
       const float* __restrict__ a3, const float* __restrict__ w4,
       const float* __restrict__ b4, const float* __restrict__ a4) {
    extern __shared__ float dsm[];
    float* sp2 = dsm;                       // 100*68 = 6800 floats (padded rows)
    float4* sw3 = (float4*)(dsm + 6800);    // 9216 f4
    float* c3b = (float*)(sw3 + 9216);      // 64*17 f4 = 4352 floats (padded)
    float* p3  = c3b + 4352;                // 1024
    int n = blockIdx.x, tid = threadIdx.x;
    const float4* src = (const float4*)(g_p2 + (size_t)n*6400);
    for (int i = tid; i < 100*16; i += 512) {
        int pos = i >> 4, sub = i & 15;
        ((float4*)sp2)[pos*17 + sub] = src[i];
    }
    for (int i = tid; i < 9216; i += 512) sw3[i] = ((const float4*)w3)[i];
    __syncthreads();
    // conv3: 16 warps = 8 oc4-pairs x 2 position-halves; lane owns 1 position
    {
        int w = tid >> 5, lane = tid & 31;
        int oc4a = 2*(w & 7);
        int pos = (w >> 3)*32 + lane;       // 0..63
        int y = pos >> 3, x = pos & 7;
        int ibase = (y*10 + x)*68;
        float4 c0 = ((const float4*)b3)[oc4a], c1 = ((const float4*)b3)[oc4a+1];
        #pragma unroll
        for (int ky = 0; ky < 3; ky++)
        #pragma unroll
        for (int kx = 0; kx < 3; kx++) {
            int koff = (ky*10 + kx)*68;
            const float4* wp = sw3 + ((ky*3 + kx)*64)*16 + oc4a;
            #pragma unroll 4
            for (int ic4 = 0; ic4 < 16; ic4++) {
                const float4* w4p = wp + ic4*64;
                float4 wa0 = w4p[0],  wb0 = w4p[1];
                float4 wa1 = w4p[16], wb1 = w4p[17];
                float4 wa2 = w4p[32], wb2 = w4p[33];
                float4 wa3 = w4p[48], wb3 = w4p[49];
                float4 iv = *(const float4*)(sp2 + ibase + koff + ic4*4);
                fma4(c0, iv.x, wa0); fma4(c1, iv.x, wb0);
                fma4(c0, iv.y, wa1); fma4(c1, iv.y, wb1);
                fma4(c0, iv.z, wa2); fma4(c1, iv.z, wb2);
                fma4(c0, iv.w, wa3); fma4(c1, iv.w, wb3);
            }
        }
        prelu4(c0, ((const float4*)a3)[oc4a]);
        prelu4(c1, ((const float4*)a3)[oc4a+1]);
        ((float4*)c3b)[pos*17 + oc4a]     = c0;
        ((float4*)c3b)[pos*17 + oc4a + 1] = c1;
    }
    __syncthreads();
    // pool 2x2 -> 4x4x64
    for (int it = tid; it < 4*4*16; it += 512) {
        int oc4 = it & 15, p = it >> 4, x = p % 4, y = p / 4;
        const float4* c4 = (const float4*)c3b;
        float4 m = c4[(2*y*8 + 2*x)*17 + oc4];
        max4(m, c4[(2*y*8 + 2*x+1)*17 + oc4]);
        max4(m, c4[((2*y+1)*8 + 2*x)*17 + oc4]);
        max4(m, c4[((2*y+1)*8 + 2*x+1)*17 + oc4]);
        ((float4*)p3)[(y*4 + x)*16 + oc4] = m;
    }
    __syncthreads();
    // conv4 2x2,64->128 -> 3x3x128, flatten NCHW (c*9 + y*3 + x)  (R8 version)
    for (int it = tid; it < 3*3*32; it += 512) {
        int oc4 = it & 31, p = it >> 5, x = p % 3, y = p / 3;
        float4 v = __ldg((const float4*)b4 + oc4);
        #pragma unroll
        for (int ky = 0; ky < 2; ky++)
        #pragma unroll
        for (int kx = 0; kx < 2; kx++) {
            const float* ip = p3 + ((y+ky)*4 + x+kx)*64;
            const float4* wp = (const float4*)w4 + ((ky*2 + kx)*64)*32 + oc4;
            #pragma unroll 8
            for (int ic = 0; ic < 64; ic++)
                fma4(v, ip[ic], __ldg(wp + ic*32));
        }
        float4 al = __ldg((const float4*)a4 + oc4);
        prelu4(v, al);
        float* hb = g_h4 + (size_t)n*1152;
        int c = oc4*4;
        hb[(c+0)*9 + y*3 + x] = v.x;
        hb[(c+1)*9 + y*3 + x] = v.y;
        hb[(c+2)*9 + y*3 + x] = v.z;
        hb[(c+3)*9 + y*3 + x] = v.w;
    }
}

// ------------- K5: fc5 (1152->256) + prelu, 8 boxes/block -------------
__global__ void k_fc5(const float* __restrict__ w, const float* __restrict__ b,
                      const float* __restrict__ a) {
    __shared__ float sa_[8*1152];
    int b0 = blockIdx.x * 8, tid = threadIdx.x;
    const float4* src = (const float4*)(g_h4 + (size_t)b0*1152);
    for (int i = tid; i < 2304; i += 256) ((float4*)sa_)[i] = src[i];
    __syncthreads();
    int o = tid;
    float bias = __ldg(b + o);
    float acc[8];
    #pragma unroll
    for (int q = 0; q < 8; q++) acc[q] = bias;
    const float4* wr = (const float4*)(w + (size_t)o*1152);
    for (int k4 = 0; k4 < 288; k4++) {
        float4 wv = __ldg(wr + k4);
        #pragma unroll
        for (int q = 0; q < 8; q++) {
            float4 av = ((const float4*)(sa_ + q*1152))[k4];
            acc[q] = fmaf(wv.x, av.x, acc[q]);
            acc[q] = fmaf(wv.y, av.y, acc[q]);
            acc[q] = fmaf(wv.z, av.z, acc[q]);
            acc[q] = fmaf(wv.w, av.w, acc[q]);
        }
    }
    float al = __ldg(a + o);
    #pragma unroll
    for (int q = 0; q < 8; q++) {
        float v = acc[q];
        g_h5[(size_t)(b0 + q)*256 + o] = v >= 0.f ? v : al * v;
    }
}

// ------------- K6: heads -------------
__global__ void k_heads(const float* __restrict__ wa, const float* __restrict__ ba,
                        const float* __restrict__ wb, const float* __restrict__ bbv) {
    int n = blockIdx.x * 8 + (threadIdx.x >> 5);
    int lane = threadIdx.x & 31;
    float h[8];
    #pragma unroll
    for (int u = 0; u < 8; u++) h[u] = g_h5[(size_t)n*256 + lane + u*32];
    float dots[6];
    #pragma unroll
    for (int d = 0; d < 6; d++) {
        const float* wr = (d < 2) ? (wa + d*256) : (wb + (d-2)*256);
        float p = 0.f;
        #pragma unroll
        for (int u = 0; u < 8; u++) p = fmaf(h[u], __ldg(wr + lane + u*32), p);
        #pragma unroll
        for (int off = 16; off; off >>= 1) p += __shfl_xor_sync(FULLMASK, p, off);
        dots[d] = p;
    }
    if (lane == 0) {
        float z0 = dots[0] + __ldg(ba+0), z1 = dots[1] + __ldg(ba+1);
        float m = fmaxf(z0, z1);
        float e0 = expf(z0 - m), e1 = expf(z1 - m);
        float score = e1 / (e0 + e1);
        float r0 = dots[2] + __ldg(bbv+0), r1 = dots[3] + __ldg(bbv+1);
        float r2 = dots[4] + __ldg(bbv+2), r3 = dots[5] + __ldg(bbv+3);
        float x1 = g_bb[n*4+0], y1 = g_bb[n*4+1], x2 = g_bb[n*4+2], y2 = g_bb[n*4+3];
        float w = x2 - x1, hh = y2 - y1;
        g_outbox[n] = make_float4(fmaf(r0,w,x1), fmaf(r1,hh,y1), fmaf(r2,w,x2), fmaf(r3,hh,y2));
        g_key[n] = (score >= 0.5f) ? score : -INFINITY;
    }
}

// ------------- K7: bitonic sort by (key desc, idx asc) -------------
__device__ __forceinline__ bool s_before(float ka, int ia, float kb, int ib) {
    return (ka > kb) || (ka == kb && ia < ib);
}
__global__ void k_sort() {
    __shared__ float sk[NB];
    __shared__ int si[NB];
    int tid = threadIdx.x;
    for (int i = tid; i < NB; i += 1024) { sk[i] = g_key[i]; si[i] = i; }
    for (int k = 2; k <= NB; k <<= 1)
        for (int j = k >> 1; j > 0; j >>= 1) {
            __syncthreads();
            for (int i = tid; i < NB; i += 1024) {
                int l = i ^ j;
                if (l > i) {
                    bool asc = ((i & k) == 0);
                    bool ib = s_before(sk[i], si[i], sk[l], si[l]);
                    if (ib != asc) {
                        float tk = sk[i]; sk[i] = sk[l]; sk[l] = tk;
                        int ti = si[i]; si[i] = si[l]; si[l] = ti;
                    }
                }
            }
        }
    __syncthreads();
    for (int r = tid; r < NB; r += 1024) {
        g_sortkey[r] = sk[r];
        g_order[r] = si[r];
        g_sortedbox[r] = g_outbox[si[r]];
    }
}

// ------------- K8: IoU suppression mask -------------
__global__ void k_mask() {
    int t = blockIdx.x * 256 + threadIdx.x;
    int i = t >> 6, wj = t & 63;
    float4 bi = g_sortedbox[i];
    float ai = (bi.z - bi.x) * (bi.w - bi.y);
    unsigned bits = 0;
    for (int u = 0; u < 32; u++) {
        int j = wj*32 + u;
        if (j > i) {
            float4 bj = g_sortedbox[j];
            float aj = (bj.z - bj.x) * (bj.w - bj.y);
            float xx1 = fmaxf(bi.x, bj.x), yy1 = fmaxf(bi.y, bj.y);
            float xx2 = fminf(bi.z, bj.z), yy2 = fminf(bi.w, bj.w);
            float inter = fmaxf(xx2 - xx1, 0.f) * fmaxf(yy2 - yy1, 0.f);
            float iou = inter / (ai + aj - inter + 1e-12f);
            if (iou > 0.5f) bits |= (1u << u);
        }
    }
    g_mask[i*64 + wj] = bits;
}

// ------------- K9: serial greedy scan (single warp) -------------
__global__ void k_scan() {
    int lane = threadIdx.x;
    unsigned r0 = 0, r1 = 0, k0 = 0, k1 = 0;
    for (int i = 0; i < NB; i++) {
        int wi = i >> 5;
        unsigned cur = (wi >= 32) ? r1 : r0;
        unsigned word = __shfl_sync(FULLMASK, cur, wi & 31);
        bool removed = (word >> (i & 31)) & 1u;
        bool valid = g_sortkey[i] >= 0.5f;
        bool kept = valid && !removed;
        if (kept) {
            r0 |= g_mask[i*64 + lane];
            r1 |= g_mask[i*64 + 32 + lane];
            if (lane == (wi & 31)) {
                if (wi >= 32) k1 |= (1u << (i & 31)); else k0 |= (1u << (i & 31));
            }
        }
    }
    g_keep[lane] = k0;
    g_keep[32 + lane] = k1;
}

// ------------- K10: scatter output -------------
__global__ void k_out(float4* __restrict__ out) {
    int r = blockIdx.x * 256 + threadIdx.x;
    int orig = g_order[r];
    bool kept = (g_keep[r >> 5] >> (r & 31)) & 1u;
    float4 b = g_sortedbox[r];
    out[orig] = kept ? b : make_float4(0.f, 0.f, 0.f, 0.f);
}

extern "C" void kernel_launch(void* const* d_in, const int* in_sizes, int n_in,
                              void* d_out, int out_size) {
    const float* bboxes  = (const float*)d_in[0];
    const float* image   = (const float*)d_in[1];
    const float* c1w = (const float*)d_in[2];  const float* c1b = (const float*)d_in[3];
    const float* p1  = (const float*)d_in[4];
    const float* c2w = (const float*)d_in[5];  const float* c2b = (const float*)d_in[6];
    const float* p2  = (const float*)d_in[7];
    const float* c3w = (const float*)d_in[8];  const float* c3b = (const float*)d_in[9];
    const float* p3  = (const float*)d_in[10];
    const float* c4w = (const float*)d_in[11]; const float* c4b = (const float*)d_in[12];
    const float* p4  = (const float*)d_in[13];
    const float* f5w = (const float*)d_in[14]; const float* f5b = (const float*)d_in[15];
    const float* p5  = (const float*)d_in[16];
    const float* f6aw = (const float*)d_in[17]; const float* f6ab = (const float*)d_in[18];
    const float* f6bw = (const float*)d_in[19]; const float* f6bb = (const float*)d_in[20];

    int smem1 = (6912 + 216*4 + 8*4 + 8*4 + 8464*4) * 4;     // 166784
    int smem2 = (19044 + (4608 + 32 + 3969) * 4) * 4;        // 213920
    int smem3 = (6800 + 9216*4 + 4352 + 1024) * 4;           // 196160
    cudaFuncSetAttribute(k_c1p1, cudaFuncAttributeMaxDynamicSharedMemorySize, smem1);
    cudaFuncSetAttribute(k_c2p2, cudaFuncAttributeMaxDynamicSharedMemorySize, smem2);
    cudaFuncSetAttribute(k_c3c4, cudaFuncAttributeMaxDynamicSharedMemorySize, smem3);

    k_crop<<<NB, 256>>>(bboxes, image);
    k_c1p1<<<NB, 512, smem1>>>(c1w, c1b, p1);
    k_c2p2<<<NB, 512, smem2>>>(c2w, c2b, p2);
    k_c3c4<<<NB, 512, smem3>>>(c3w, c3b, p3, c4w, c4b, p4);
    k_fc5<<<NB/8, 256>>>(f5w, f5b, p5);
    k_heads<<<NB/8, 256>>>(f6aw, f6ab, f6bw, f6bb);
    k_sort<<<1, 1024>>>();
    k_mask<<<NB*64/256, 256>>>();
    k_scan<<<1, 32>>>();
    k_out<<<NB/256, 256>>>((float4*)d_out);
}

// round 12
// speedup vs baseline: 3.9433x; 1.1176x over previous
#include <cuda_runtime.h>
#include <math.h>

#define NB 2048
#define FULLMASK 0xffffffffu

// ------------- scratch -------------
__device__ float g_crops[NB*48*48*3];
__device__ float g_bb[NB*4];
__device__ float g_p1[NB*23*23*32];
__device__ float g_p2[NB*10*10*64];
__device__ float g_h4[NB*1152];
__device__ float g_h5[NB*256];
__device__ float4 g_outbox[NB];
__device__ float  g_key[NB];
__device__ int    g_order[NB];
__device__ float  g_sortkey[NB];
__device__ float4 g_sortedbox[NB];
__device__ unsigned g_mask[NB*64];
__device__ unsigned g_keep[64];

__device__ __forceinline__ void fma4(float4& v, float s, const float4 wv) {
    v.x = fmaf(s, wv.x, v.x); v.y = fmaf(s, wv.y, v.y);
    v.z = fmaf(s, wv.z, v.z); v.w = fmaf(s, wv.w, v.w);
}
__device__ __forceinline__ void prelu4(float4& v, const float4 al) {
    v.x = v.x >= 0.f ? v.x : al.x * v.x; v.y = v.y >= 0.f ? v.y : al.y * v.y;
    v.z = v.z >= 0.f ? v.z : al.z * v.z; v.w = v.w >= 0.f ? v.w : al.w * v.w;
}
__device__ __forceinline__ void max4(float4& m, const float4 v) {
    m.x = fmaxf(m.x, v.x); m.y = fmaxf(m.y, v.y);
    m.z = fmaxf(m.z, v.z); m.w = fmaxf(m.w, v.w);
}

// ------------- K1: crop + normalize -------------
__global__ void k_crop(const float* __restrict__ bboxes, const float* __restrict__ image) {
    int n = blockIdx.x, tid = threadIdx.x;
    __shared__ int sxs[48], sys[48];
    __shared__ float sbb[4];
    if (tid < 4) {
        float v = bboxes[n*4 + tid];
        v = (tid < 2) ? fmaxf(v, 0.f) : fminf(v, 1024.f);
        sbb[tid] = v; g_bb[n*4 + tid] = v;
    }
    __syncthreads();
    if (tid < 48) {
        int ix1 = (int)sbb[0], iy1 = (int)sbb[1], ix2 = (int)sbb[2], iy2 = (int)sbb[3];
        int cw = max(ix2 - ix1, 1), ch = max(iy2 - iy1, 1);
        sxs[tid] = ix1 + (tid * cw) / 48;
        sys[tid] = iy1 + (tid * ch) / 48;
    }
    __syncthreads();
    for (int p = tid; p < 48*48; p += blockDim.x) {
        int i = p / 48, j = p - i*48;
        const float* src = image + (sys[i]*1024 + sxs[j])*3;
        float* dst = g_crops + (size_t)((n*48 + i)*48 + j)*3;
        dst[0] = (src[0] - 127.5f) * 0.0078125f;
        dst[1] = (src[1] - 127.5f) * 0.0078125f;
        dst[2] = (src[2] - 127.5f) * 0.0078125f;
    }
}

// ------------- K2: conv1(3x3,3->32)+prelu -> smem, then pool(3,2,p1) -> 23x23x32
__global__ void __launch_bounds__(512, 1)
k_c1p1(const float* __restrict__ w1, const float* __restrict__ b1,
       const float* __restrict__ a1) {
    extern __shared__ float dsm[];
    float* sc = dsm;                         // 6912
    float4* sw = (float4*)(dsm + 6912);      // 216 f4
    float4* sb4 = sw + 216;                  // 8
    float4* sa4 = sb4 + 8;                   // 8
    float4* cbuf = sa4 + 8;                  // 46*46*4 = 8464 f4
    int n = blockIdx.x, tid = threadIdx.x;
    const float4* src = (const float4*)(g_crops + (size_t)n*6912);
    for (int i = tid; i < 1728; i += 512) ((float4*)sc)[i] = src[i];
    for (int i = tid; i < 216; i += 512) sw[i] = ((const float4*)w1)[i];
    if (tid < 8) { sb4[tid] = ((const float4*)b1)[tid]; sa4[tid] = ((const float4*)a1)[tid]; }
    __syncthreads();
    #pragma unroll
    for (int pass = 0; pass < 2; pass++) {
        int ocb = pass * 4;
        for (int it = tid; it < 46*46*4; it += 512) {
            int oc4 = it & 3, pos = it >> 2, r = pos / 46, c = pos - r*46;
            float4 v = sb4[ocb + oc4];
            #pragma unroll
            for (int ky = 0; ky < 3; ky++)
            #pragma unroll
            for (int kx = 0; kx < 3; kx++) {
                const float* ip = sc + ((r+ky)*48 + (c+kx))*3;
                int wi = ((ky*3 + kx)*3)*8 + ocb + oc4;
                fma4(v, ip[0], sw[wi]);
                fma4(v, ip[1], sw[wi + 8]);
                fma4(v, ip[2], sw[wi + 16]);
            }
            prelu4(v, sa4[ocb + oc4]);
            cbuf[pos*4 + oc4] = v;
        }
        __syncthreads();
        for (int it = tid; it < 23*23*4; it += 512) {
            int oc4 = it & 3, p = it >> 2, i = p % 23, j = p / 23;
            float4 m = make_float4(-3.4e38f, -3.4e38f, -3.4e38f, -3.4e38f);
            #pragma unroll
            for (int dr = -1; dr < 2; dr++) {
                int r = 2*j + dr; if (r < 0 || r > 45) continue;
                #pragma unroll
                for (int dc = -1; dc < 2; dc++) {
                    int c = 2*i + dc; if (c < 0 || c > 45) continue;
                    max4(m, cbuf[(r*46 + c)*4 + oc4]);
                }
            }
            ((float4*)(g_p1 + (size_t)n*16928))[(j*23 + i)*8 + ocb + oc4] = m;
        }
        __syncthreads();
    }
}

// ------------- K3: conv2(3x3,32->64)+prelu -> smem, then pool(3,2,p0) -> 10x10x64
__global__ void __launch_bounds__(512, 1)
k_c2p2(const float* __restrict__ w2, const float* __restrict__ b2,
       const float* __restrict__ a2) {
    extern __shared__ float dsm[];
    float* sp1 = dsm;                       // 529*36 = 19044 floats (padded rows)
    float4* sw2 = (float4*)(dsm + 19044);   // 4608 f4
    float4* sb = sw2 + 4608;                // 16
    float4* sa = sb + 16;                   // 16
    float4* cbuf = sa + 16;                 // 441*9 = 3969 f4 (padded)
    int n = blockIdx.x, tid = threadIdx.x;
    const float4* src = (const float4*)(g_p1 + (size_t)n*16928);
    for (int i = tid; i < 529*8; i += 512) {
        int pos = i >> 3, sub = i & 7;
        ((float4*)sp1)[pos*9 + sub] = src[i];
    }
    for (int i = tid; i < 4608; i += 512) sw2[i] = ((const float4*)w2)[i];
    if (tid < 16) { sb[tid] = ((const float4*)b2)[tid]; sa[tid] = ((const float4*)a2)[tid]; }
    __syncthreads();
    int w = tid >> 5, lane = tid & 31;
    int chunk = w >> 2;
    int ocp = w & 3;
    int posr[4], ib[4];
    #pragma unroll
    for (int t = 0; t < 4; t++) {
        int pos = chunk*128 + lane + 32*t;
        posr[t] = pos;
        int pc = pos > 440 ? 440 : pos;
        int r = pc / 21, c = pc - r*21;
        ib[t] = (r*23 + c)*36;
    }
    #pragma unroll
    for (int pass = 0; pass < 2; pass++) {
        int oc4a = pass*8 + 2*ocp;
        float4 a0[4], a1[4];
        float4 bias0 = sb[oc4a], bias1 = sb[oc4a+1];
        #pragma unroll
        for (int t = 0; t < 4; t++) { a0[t] = bias0; a1[t] = bias1; }
        #pragma unroll
        for (int ky = 0; ky < 3; ky++)
        #pragma unroll
        for (int kx = 0; kx < 3; kx++) {
            int koff = (ky*23 + kx)*36;
            const float4* wp = sw2 + ((ky*3 + kx)*32)*16 + oc4a;
            #pragma unroll
            for (int ic4 = 0; ic4 < 8; ic4++) {
                const float4* w4 = wp + ic4*64;
                float4 wa0 = w4[0],  wb0 = w4[1];
                float4 wa1 = w4[16], wb1 = w4[17];
                float4 wa2 = w4[32], wb2 = w4[33];
                float4 wa3 = w4[48], wb3 = w4[49];
                #pragma unroll
                for (int t = 0; t < 4; t++) {
                    float4 iv = *(const float4*)(sp1 + ib[t] + koff + ic4*4);
                    fma4(a0[t], iv.x, wa0); fma4(a1[t], iv.x, wb0);
                    fma4(a0[t], iv.y, wa1); fma4(a1[t], iv.y, wb1);
                    fma4(a0[t], iv.z, wa2); fma4(a1[t], iv.z, wb2);
                    fma4(a0[t], iv.w, wa3); fma4(a1[t], iv.w, wb3);
                }
            }
        }
        float4 al0 = sa[oc4a], al1 = sa[oc4a+1];
        #pragma unroll
        for (int t = 0; t < 4; t++) {
            if (posr[t] < 441) {
                float4 v0 = a0[t]; prelu4(v0, al0);
                float4 v1 = a1[t]; prelu4(v1, al1);
                cbuf[posr[t]*9 + 2*ocp]     = v0;
                cbuf[posr[t]*9 + 2*ocp + 1] = v1;
            }
        }
        __syncthreads();
        for (int it = tid; it < 10*10*8; it += 512) {
            int oc4l = it & 7, p = it >> 3, i = p % 10, j = p / 10;
            float4 m = cbuf[((2*j)*21 + 2*i)*9 + oc4l];
            #pragma unroll
            for (int dr = 0; dr < 3; dr++)
            #pragma unroll
            for (int dc = 0; dc < 3; dc++) {
                if (dr == 0 && dc == 0) continue;
                max4(m, cbuf[((2*j+dr)*21 + 2*i+dc)*9 + oc4l]);
            }
            ((float4*)(g_p2 + (size_t)n*6400))[(j*10 + i)*16 + pass*8 + oc4l] = m;
        }
        __syncthreads();
    }
}

// ------------- K4: conv3(warp-per-oc4-pair)+prelu+pool(2,2) + conv4(w4 in smem)+prelu + flatten
__global__ void __launch_bounds__(512, 1)
k_c3c4(const float* __restrict__ w3, const float* __restrict__ b3,
       const float* __restrict__ a3, const float* __restrict__ w4,
       const float* __restrict__ b4, const float* __restrict__ a4) {
    extern __shared__ float dsm[];
    float* sp2 = dsm;                       // 100*68 = 6800 floats (padded rows)
    float4* sw3 = (float4*)(dsm + 6800);    // 9216 f4 (reused as w4: 8192 f4)
    float* c3b = (float*)(sw3 + 9216);      // 64*17 f4 = 4352 floats (padded)
    float* p3  = c3b + 4352;                // 1024
    int n = blockIdx.x, tid = threadIdx.x;
    const float4* src = (const float4*)(g_p2 + (size_t)n*6400);
    for (int i = tid; i < 100*16; i += 512) {
        int pos = i >> 4, sub = i & 15;
        ((float4*)sp2)[pos*17 + sub] = src[i];
    }
    for (int i = tid; i < 9216; i += 512) sw3[i] = ((const float4*)w3)[i];
    __syncthreads();
    // conv3: 16 warps = 8 oc4-pairs x 2 position-halves; lane owns 1 position
    {
        int w = tid >> 5, lane = tid & 31;
        int oc4a = 2*(w & 7);
        int pos = (w >> 3)*32 + lane;
        int y = pos >> 3, x = pos & 7;
        int ibase = (y*10 + x)*68;
        float4 c0 = ((const float4*)b3)[oc4a], c1 = ((const float4*)b3)[oc4a+1];
        #pragma unroll
        for (int ky = 0; ky < 3; ky++)
        #pragma unroll
        for (int kx = 0; kx < 3; kx++) {
            int koff = (ky*10 + kx)*68;
            const float4* wp = sw3 + ((ky*3 + kx)*64)*16 + oc4a;
            #pragma unroll 4
            for (int ic4 = 0; ic4 < 16; ic4++) {
                const float4* w4p = wp + ic4*64;
                float4 wa0 = w4p[0],  wb0 = w4p[1];
                float4 wa1 = w4p[16], wb1 = w4p[17];
                float4 wa2 = w4p[32], wb2 = w4p[33];
                float4 wa3 = w4p[48], wb3 = w4p[49];
                float4 iv = *(const float4*)(sp2 + ibase + koff + ic4*4);
                fma4(c0, iv.x, wa0); fma4(c1, iv.x, wb0);
                fma4(c0, iv.y, wa1); fma4(c1, iv.y, wb1);
                fma4(c0, iv.z, wa2); fma4(c1, iv.z, wb2);
                fma4(c0, iv.w, wa3); fma4(c1, iv.w, wb3);
            }
        }
        prelu4(c0, ((const float4*)a3)[oc4a]);
        prelu4(c1, ((const float4*)a3)[oc4a+1]);
        ((float4*)c3b)[pos*17 + oc4a]     = c0;
        ((float4*)c3b)[pos*17 + oc4a + 1] = c1;
    }
    __syncthreads();
    // pool 2x2 -> 4x4x64, AND stage w4 into the (now dead) sw3 region
    float4* sw4 = sw3;  // reuse
    for (int it = tid; it < 4*4*16; it += 512) {
        int oc4 = it & 15, p = it >> 4, x = p % 4, y = p / 4;
        const float4* c4 = (const float4*)c3b;
        float4 m = c4[(2*y*8 + 2*x)*17 + oc4];
        max4(m, c4[(2*y*8 + 2*x+1)*17 + oc4]);
        max4(m, c4[((2*y+1)*8 + 2*x)*17 + oc4]);
        max4(m, c4[((2*y+1)*8 + 2*x+1)*17 + oc4]);
        ((float4*)p3)[(y*4 + x)*16 + oc4] = m;
    }
    for (int i = tid; i < 8192; i += 512) sw4[i] = ((const float4*)w4)[i];
    __syncthreads();
    // conv4 2x2,64->128 -> 3x3x128, weights from smem, flatten NCHW (c*9 + y*3 + x)
    for (int it = tid; it < 3*3*32; it += 512) {
        int oc4 = it & 31, p = it >> 5, x = p % 3, y = p / 3;
        float4 v = __ldg((const float4*)b4 + oc4);
        #pragma unroll
        for (int ky = 0; ky < 2; ky++)
        #pragma unroll
        for (int kx = 0; kx < 2; kx++) {
            const float* ip = p3 + ((y+ky)*4 + x+kx)*64;
            const float4* wp = sw4 + ((ky*2 + kx)*64)*32 + oc4;
            #pragma unroll 8
            for (int ic = 0; ic < 64; ic++)
                fma4(v, ip[ic], wp[ic*32]);
        }
        float4 al = __ldg((const float4*)a4 + oc4);
        prelu4(v, al);
        float* hb = g_h4 + (size_t)n*1152;
        int c = oc4*4;
        hb[(c+0)*9 + y*3 + x] = v.x;
        hb[(c+1)*9 + y*3 + x] = v.y;
        hb[(c+2)*9 + y*3 + x] = v.z;
        hb[(c+3)*9 + y*3 + x] = v.w;
    }
}

// ------------- K5: fc5 (1152->256) + prelu, 8 boxes/block -------------
__global__ void k_fc5(const float* __restrict__ w, const float* __restrict__ b,
                      const float* __restrict__ a) {
    __shared__ float sa_[8*1152];
    int b0 = blockIdx.x * 8, tid = threadIdx.x;
    const float4* src = (const float4*)(g_h4 + (size_t)b0*1152);
    for (int i = tid; i < 2304; i += 256) ((float4*)sa_)[i] = src[i];
    __syncthreads();
    int o = tid;
    float bias = __ldg(b + o);
    float acc[8];
    #pragma unroll
    for (int q = 0; q < 8; q++) acc[q] = bias;
    const float4* wr = (const float4*)(w + (size_t)o*1152);
    for (int k4 = 0; k4 < 288; k4++) {
        float4 wv = __ldg(wr + k4);
        #pragma unroll
        for (int q = 0; q < 8; q++) {
            float4 av = ((const float4*)(sa_ + q*1152))[k4];
            acc[q] = fmaf(wv.x, av.x, acc[q]);
            acc[q] = fmaf(wv.y, av.y, acc[q]);
            acc[q] = fmaf(wv.z, av.z, acc[q]);
            acc[q] = fmaf(wv.w, av.w, acc[q]);
        }
    }
    float al = __ldg(a + o);
    #pragma unroll
    for (int q = 0; q < 8; q++) {
        float v = acc[q];
        g_h5[(size_t)(b0 + q)*256 + o] = v >= 0.f ? v : al * v;
    }
}

// ------------- K6: heads -------------
__global__ void k_heads(const float* __restrict__ wa, const float* __restrict__ ba,
                        const float* __restrict__ wb, const float* __restrict__ bbv) {
    int n = blockIdx.x * 8 + (threadIdx.x >> 5);
    int lane = threadIdx.x & 31;
    float h[8];
    #pragma unroll
    for (int u = 0; u < 8; u++) h[u] = g_h5[(size_t)n*256 + lane + u*32];
    float dots[6];
    #pragma unroll
    for (int d = 0; d < 6; d++) {
        const float* wr = (d < 2) ? (wa + d*256) : (wb + (d-2)*256);
        float p = 0.f;
        #pragma unroll
        for (int u = 0; u < 8; u++) p = fmaf(h[u], __ldg(wr + lane + u*32), p);
        #pragma unroll
        for (int off = 16; off; off >>= 1) p += __shfl_xor_sync(FULLMASK, p, off);
        dots[d] = p;
    }
    if (lane == 0) {
        float z0 = dots[0] + __ldg(ba+0), z1 = dots[1] + __ldg(ba+1);
        float m = fmaxf(z0, z1);
        float e0 = expf(z0 - m), e1 = expf(z1 - m);
        float score = e1 / (e0 + e1);
        float r0 = dots[2] + __ldg(bbv+0), r1 = dots[3] + __ldg(bbv+1);
        float r2 = dots[4] + __ldg(bbv+2), r3 = dots[5] + __ldg(bbv+3);
        float x1 = g_bb[n*4+0], y1 = g_bb[n*4+1], x2 = g_bb[n*4+2], y2 = g_bb[n*4+3];
        float w = x2 - x1, hh = y2 - y1;
        g_outbox[n] = make_float4(fmaf(r0,w,x1), fmaf(r1,hh,y1), fmaf(r2,w,x2), fmaf(r3,hh,y2));
        g_key[n] = (score >= 0.5f) ? score : -INFINITY;
    }
}

// ------------- K7: bitonic sort by (key desc, idx asc) -------------
__device__ __forceinline__ bool s_before(float ka, int ia, float kb, int ib) {
    return (ka > kb) || (ka == kb && ia < ib);
}
__global__ void k_sort() {
    __shared__ float sk[NB];
    __shared__ int si[NB];
    int tid = threadIdx.x;
    for (int i = tid; i < NB; i += 1024) { sk[i] = g_key[i]; si[i] = i; }
    for (int k = 2; k <= NB; k <<= 1)
        for (int j = k >> 1; j > 0; j >>= 1) {
            __syncthreads();
            for (int i = tid; i < NB; i += 1024) {
                int l = i ^ j;
                if (l > i) {
                    bool asc = ((i & k) == 0);
                    bool ib = s_before(sk[i], si[i], sk[l], si[l]);
                    if (ib != asc) {
                        float tk = sk[i]; sk[i] = sk[l]; sk[l] = tk;
                        int ti = si[i]; si[i] = si[l]; si[l] = ti;
                    }
                }
            }
        }
    __syncthreads();
    for (int r = tid; r < NB; r += 1024) {
        g_sortkey[r] = sk[r];
        g_order[r] = si[r];
        g_sortedbox[r] = g_outbox[si[r]];
    }
}

// ------------- K8: IoU suppression mask -------------
__global__ void k_mask() {
    int t = blockIdx.x * 256 + threadIdx.x;
    int i = t >> 6, wj = t & 63;
    float4 bi = g_sortedbox[i];
    float ai = (bi.z - bi.x) * (bi.w - bi.y);
    unsigned bits = 0;
    for (int u = 0; u < 32; u++) {
        int j = wj*32 + u;
        if (j > i) {
            float4 bj = g_sortedbox[j];
            float aj = (bj.z - bj.x) * (bj.w - bj.y);
            float xx1 = fmaxf(bi.x, bj.x), yy1 = fmaxf(bi.y, bj.y);
            float xx2 = fminf(bi.z, bj.z), yy2 = fminf(bi.w, bj.w);
            float inter = fmaxf(xx2 - xx1, 0.f) * fmaxf(yy2 - yy1, 0.f);
            float iou = inter / (ai + aj - inter + 1e-12f);
            if (iou > 0.5f) bits |= (1u << u);
        }
    }
    g_mask[i*64 + wj] = bits;
}

// ------------- K9: serial greedy scan (single warp, double-buffered prefetch) -------------
__global__ void k_scan() {
    __shared__ float sk[NB];
    int lane = threadIdx.x;
    for (int i = lane; i < NB; i += 32) sk[i] = g_sortkey[i];
    __syncwarp();
    unsigned r0 = 0, r1 = 0, k0 = 0, k1 = 0;
    unsigned m0[8], m1[8], n0[8], n1[8];
    #pragma unroll
    for (int t = 0; t < 8; t++) {
        m0[t] = g_mask[t*64 + lane];
        m1[t] = g_mask[t*64 + 32 + lane];
    }
    for (int base = 0; base < NB; base += 8) {
        if (base + 8 < NB) {
            #pragma unroll
            for (int t = 0; t < 8; t++) {
                n0[t] = g_mask[(base+8+t)*64 + lane];
                n1[t] = g_mask[(base+8+t)*64 + 32 + lane];
            }
        }
        #pragma unroll
        for (int t = 0; t < 8; t++) {
            int i = base + t;
            int wi = i >> 5;
            unsigned cur = (wi >= 32) ? r1 : r0;
            unsigned word = __shfl_sync(FULLMASK, cur, wi & 31);
            bool removed = (word >> (i & 31)) & 1u;
            bool kept = (sk[i] >= 0.5f) && !removed;
            if (kept) {
                r0 |= m0[t];
                r1 |= m1[t];
                if (lane == (wi & 31)) {
                    if (wi >= 32) k1 |= (1u << (i & 31)); else k0 |= (1u << (i & 31));
                }
            }
        }
        #pragma unroll
        for (int t = 0; t < 8; t++) { m0[t] = n0[t]; m1[t] = n1[t]; }
    }
    g_keep[lane] = k0;
    g_keep[32 + lane] = k1;
}

// ------------- K10: scatter output -------------
__global__ void k_out(float4* __restrict__ out) {
    int r = blockIdx.x * 256 + threadIdx.x;
    int orig = g_order[r];
    bool kept = (g_keep[r >> 5] >> (r & 31)) & 1u;
    float4 b = g_sortedbox[r];
    out[orig] = kept ? b : make_float4(0.f, 0.f, 0.f, 0.f);
}

extern "C" void kernel_launch(void* const* d_in, const int* in_sizes, int n_in,
                              void* d_out, int out_size) {
    const float* bboxes  = (const float*)d_in[0];
    const float* image   = (const float*)d_in[1];
    const float* c1w = (const float*)d_in[2];  const float* c1b = (const float*)d_in[3];
    const float* p1  = (const float*)d_in[4];
    const float* c2w = (const float*)d_in[5];  const float* c2b = (const float*)d_in[6];
    const float* p2  = (const float*)d_in[7];
    const float* c3w = (const float*)d_in[8];  const float* c3b = (const float*)d_in[9];
    const float* p3  = (const float*)d_in[10];
    const float* c4w = (const float*)d_in[11]; const float* c4b = (const float*)d_in[12];
    const float* p4  = (const float*)d_in[13];
    const float* f5w = (const float*)d_in[14]; const float* f5b = (const float*)d_in[15];
    const float* p5  = (const float*)d_in[16];
    const float* f6aw = (const float*)d_in[17]; const float* f6ab = (const float*)d_in[18];
    const float* f6bw = (const float*)d_in[19]; const float* f6bb = (const float*)d_in[20];

    int smem1 = (6912 + 216*4 + 8*4 + 8*4 + 8464*4) * 4;     // 166784
    int smem2 = (19044 + (4608 + 32 + 3969) * 4) * 4;        // 213920
    int smem3 = (6800 + 9216*4 + 4352 + 1024) * 4;           // 196160
    cudaFuncSetAttribute(k_c1p1, cudaFuncAttributeMaxDynamicSharedMemorySize, smem1);
    cudaFuncSetAttribute(k_c2p2, cudaFuncAttributeMaxDynamicSharedMemorySize, smem2);
    cudaFuncSetAttribute(k_c3c4, cudaFuncAttributeMaxDynamicSharedMemorySize, smem3);

    k_crop<<<NB, 256>>>(bboxes, image);
    k_c1p1<<<NB, 512, smem1>>>(c1w, c1b, p1);
    k_c2p2<<<NB, 512, smem2>>>(c2w, c2b, p2);
    k_c3c4<<<NB, 512, smem3>>>(c3w, c3b, p3, c4w, c4b, p4);
    k_fc5<<<NB/8, 256>>>(f5w, f5b, p5);
    k_heads<<<NB/8, 256>>>(f6aw, f6ab, f6bw, f6bb);
    k_sort<<<1, 1024>>>();
    k_mask<<<NB*64/256, 256>>>();
    k_scan<<<1, 32>>>();
    k_out<<<NB/256, 256>>>((float4*)d_out);
}